// round 9
// baseline (speedup 1.0000x reference)
#include <cuda_runtime.h>
#include <cstdint>

#define SEQ   256
#define BATCH 8192

// pack two f32 -> f16x2 (lo = first arg)
__device__ __forceinline__ uint32_t pkh(float lo, float hi) {
    uint32_t u; asm("cvt.rn.f16x2.f32 %0, %2, %1;" : "=r"(u) : "f"(lo), "f"(hi)); return u;
}
__device__ __forceinline__ void mma16(float d[4], const uint32_t a[4], uint32_t b0, uint32_t b1) {
    asm("mma.sync.aligned.m16n8k16.row.col.f32.f16.f16.f32 "
        "{%0,%1,%2,%3},{%4,%5,%6,%7},{%8,%9},{%0,%1,%2,%3};"
        : "+f"(d[0]), "+f"(d[1]), "+f"(d[2]), "+f"(d[3])
        : "r"(a[0]), "r"(a[1]), "r"(a[2]), "r"(a[3]), "r"(b0), "r"(b1));
}
__device__ __forceinline__ float sig_t(float x) {
    float t; asm("tanh.approx.f32 %0, %1;" : "=f"(t) : "f"(0.5f * x));
    return fmaf(t, 0.5f, 0.5f);
}
__device__ __forceinline__ float tanh_ap(float x) {
    float t; asm("tanh.approx.f32 %0, %1;" : "=f"(t) : "f"(x)); return t;
}

// Grid: 128 blocks x 512 threads (16 warps = 4 groups of 4 warps).
// Group G = blockIdx.x*4 + (wid>>2) owns rows [16G, 16G+16).
// Warp q = wid&3 owns hidden-unit columns [8q, 8q+8).
// Lane: g = lane>>2 (rows g, g+8), tg = lane&3.
// ONE barrier per step; h/y exchanged via parity (ping-pong) buffers.
// Exchange rows store f16x2 words permuted: word w -> slot (w%4)*4 + w/4,
// so LOAD_A is 2x LDS.128 per state.
__global__ void __launch_bounds__(512, 1) gru2_hmma5_kernel(
    const float* __restrict__ x,
    const float* __restrict__ h_in,
    const float* __restrict__ Wih0,
    const float* __restrict__ Whh0,
    const float* __restrict__ bih0,
    const float* __restrict__ bhh0,
    const float* __restrict__ Wih1,
    const float* __restrict__ Whh1,
    const float* __restrict__ bih1,
    const float* __restrict__ bhh1,
    const float* __restrict__ Wout,
    const float* __restrict__ bout,
    float* __restrict__ out)
{
    __shared__ __align__(16) uint4  BW[36 * 32];        // 18432 B
    __shared__ float4 cA4s[32];
    __shared__ float4 cB0s[32];
    __shared__ float4 cB1s[32];
    __shared__ __align__(16) uint32_t hs0[2 * 4 * 320]; // [buf][grp][16 rows x 20]
    __shared__ __align__(16) uint32_t hs1[2 * 4 * 320];
    __shared__ float  yS[2 * 4 * 64];                   // [buf][grp][4q x 16 rows]
    __shared__ float  boS;

    const int tid = threadIdx.x;

    // B-fragment table: per quarter q4 (cols 8q4..8q4+8), 9 uint4 slots (as R8)
    for (int idx = tid; idx < 36 * 32; idx += 512) {
        int blkid = idx >> 5, l = idx & 31, gg = l >> 2, tt = l & 3;
        int q4 = blkid / 9, t = blkid - q4 * 9;
        const float* src; int rowb;
        if (t < 3)       { src = Whh0; rowb = t * 32 + 8 * q4; }
        else if (t == 3) { src = Wih1; rowb = 8 * q4; }
        else if (t == 4) { src = Whh1; rowb = 8 * q4; }
        else if (t == 5) { src = Wih1; rowb = 32 + 8 * q4; }
        else if (t == 6) { src = Whh1; rowb = 32 + 8 * q4; }
        else if (t == 7) { src = Wih1; rowb = 64 + 8 * q4; }
        else             { src = Whh1; rowb = 64 + 8 * q4; }
        const float* wr = src + (rowb + gg) * 32 + 2 * tt;
        BW[idx] = make_uint4(pkh(wr[0],  wr[1]),  pkh(wr[8],  wr[9]),
                             pkh(wr[16], wr[17]), pkh(wr[24], wr[25]));
    }
    if (tid < 32) {
        int j = tid;
        cA4s[j] = make_float4(Wih0[j], Wih0[32 + j], Wih0[64 + j], bih0[64 + j]);
        cB0s[j] = make_float4(bih0[j] + bhh0[j], bih0[32 + j] + bhh0[32 + j],
                              bhh0[64 + j], Wout[j]);
        cB1s[j] = make_float4(bih1[j] + bhh1[j], bih1[32 + j] + bhh1[32 + j],
                              bih1[64 + j], bhh1[64 + j]);
    }
    if (tid == 0) boS = bout[0];
    __syncthreads();

    const int wid  = tid >> 5;
    const int lane = tid & 31;
    const int gib  = wid >> 2;
    const int q    = wid & 3;
    const int G    = blockIdx.x * 4 + gib;

    const int g  = lane >> 2;
    const int tg = lane & 3;
    const int base = G * 16;
    const int barId = 1 + gib;
    const int colb = q * 8;
    const uint4* BWs = BW + q * 9 * 32;
    const float bo = boS;

    uint32_t* hx0base = hs0 + gib * 320;
    uint32_t* hx1base = hs1 + gib * 320;
    float*    yPbase  = yS  + gib * 64;

#define BARP() asm volatile("bar.sync %0, 128;" :: "r"(barId) : "memory")

    float4 cAr[2], cB0r[2], cB1r[2];
#pragma unroll
    for (int c = 0; c < 2; c++) {
        int j = colb + 2 * tg + c;
        cAr[c]  = cA4s[j];
        cB0r[c] = cB0s[j];
        cB1r[c] = cB1s[j];
    }

    float h0D[4], h1D[4];
#pragma unroll
    for (int rr = 0; rr < 2; rr++) {
        size_t r0 = (size_t)(base + g + 8 * rr) * 32 + colb + 2 * tg;
        float2 v0 = *(const float2*)&h_in[r0];
        float2 v1 = *(const float2*)&h_in[(size_t)BATCH * 32 + r0];
        h0D[rr * 2] = v0.x; h0D[rr * 2 + 1] = v0.y;
        h1D[rr * 2] = v1.x; h1D[rr * 2 + 1] = v1.y;
    }

    uint32_t h0A[8], h1A[8];

    // store permuted word slot 4*tg + q for own cols, rows g and g+8
#define STORE_H(hD, hx)                                                          \
    do {                                                                         \
        _Pragma("unroll")                                                        \
        for (int rr = 0; rr < 2; rr++)                                           \
            hx[(g + 8 * rr) * 20 + 4 * tg + q] = pkh(hD[rr * 2], hD[rr * 2 + 1]); \
    } while (0)

    // 2x LDS.128: row g gives hA[0,2,4,6], row g+8 gives hA[1,3,5,7]
#define LOAD_A(hx, hA)                                                           \
    do {                                                                         \
        uint4 v0 = *(const uint4*)&hx[g * 20 + 4 * tg];                          \
        uint4 v1 = *(const uint4*)&hx[(g + 8) * 20 + 4 * tg];                    \
        hA[0] = v0.x; hA[2] = v0.y; hA[4] = v0.z; hA[6] = v0.w;                  \
        hA[1] = v1.x; hA[3] = v1.y; hA[5] = v1.z; hA[7] = v1.w;                  \
    } while (0)

    // initial: h0 -> buf1 (loop iter0 writes buf0), h1 -> buf0 (read at iter0)
    STORE_H(h0D, (hx0base + 1280));
    STORE_H(h1D, hx1base);
    BARP();
    LOAD_A((hx0base + 1280), h0A);

    float xc0 = __ldg(x + base + g);
    float xc8 = __ldg(x + base + g + 8);

    for (int st = 0; st < SEQ; st++) {
        const int rb = st & 1;
        uint32_t* hx0b = hx0base + rb * 1280;
        uint32_t* hx1b = hx1base + rb * 1280;
        uint32_t* hx1n = hx1base + (rb ^ 1) * 1280;
        float* yPr = yPbase + rb * 256;
        float* yPw = yPbase + (rb ^ 1) * 256;

        const size_t nxt = (size_t)min(st + 1, SEQ - 1) * BATCH;
        float xn0 = __ldg(x + nxt + base + g);
        float xn8 = __ldg(x + nxt + base + g + 8);

        // ---------- layer 0 ----------
        float Dr[4] = {0, 0, 0, 0}, Dz[4] = {0, 0, 0, 0}, Dn[4] = {0, 0, 0, 0};
        {
            uint4 Br = BWs[0 * 32 + lane];
            uint4 Bz = BWs[1 * 32 + lane];
            uint4 Bn = BWs[2 * 32 + lane];
            mma16(Dr, h0A, Br.x, Br.y); mma16(Dr, h0A + 4, Br.z, Br.w);
            mma16(Dz, h0A, Bz.x, Bz.y); mma16(Dz, h0A + 4, Bz.z, Bz.w);
            mma16(Dn, h0A, Bn.x, Bn.y); mma16(Dn, h0A + 4, Bn.z, Bn.w);
        }
#pragma unroll
        for (int c = 0; c < 2; c++) {
            const float4 A  = cAr[c];
            const float4 Bc = cB0r[c];
#pragma unroll
            for (int rr = 0; rr < 2; rr++) {
                const float xv = rr ? xc8 : xc0;
                const int di = rr * 2 + c;
                float r = sig_t(fmaf(xv, A.x, Dr[di] + Bc.x));
                float z = sig_t(fmaf(xv, A.y, Dz[di] + Bc.y));
                float n = tanh_ap(fmaf(xv, A.z, A.w) + r * (Dn[di] + Bc.z));
                float hold = h0D[di];
                h0D[di] = n + z * (hold - n);
            }
        }
        STORE_H(h0D, hx0b);
        BARP();                     // the ONLY barrier this step
        LOAD_A(hx0b, h0A);
        LOAD_A(hx1b, h1A);          // h1 state from step st-1 (stored pre-bar)
        if (q == 0 && tg == 0 && st > 0) {
            // y for step st-1 (partials written pre-bar last step)
            out[(size_t)(st - 1) * BATCH + base + g] =
                yPr[g] + yPr[16 + g] + yPr[32 + g] + yPr[48 + g] + bo;
            out[(size_t)(st - 1) * BATCH + base + g + 8] =
                yPr[g + 8] + yPr[16 + g + 8] + yPr[32 + g + 8] + yPr[48 + g + 8] + bo;
        }

        // ---------- layer 1 ----------
        float Er[4] = {0, 0, 0, 0}, Ez[4] = {0, 0, 0, 0};
        float Ein[4] = {0, 0, 0, 0}, Ehn[4] = {0, 0, 0, 0};
        {
            uint4 Bri = BWs[3 * 32 + lane];
            uint4 Brh = BWs[4 * 32 + lane];
            uint4 Bzi = BWs[5 * 32 + lane];
            uint4 Bzh = BWs[6 * 32 + lane];
            uint4 Bin = BWs[7 * 32 + lane];
            uint4 Bhn = BWs[8 * 32 + lane];
            mma16(Er, h0A, Bri.x, Bri.y); mma16(Er, h0A + 4, Bri.z, Bri.w);
            mma16(Er, h1A, Brh.x, Brh.y); mma16(Er, h1A + 4, Brh.z, Brh.w);
            mma16(Ez, h0A, Bzi.x, Bzi.y); mma16(Ez, h0A + 4, Bzi.z, Bzi.w);
            mma16(Ez, h1A, Bzh.x, Bzh.y); mma16(Ez, h1A + 4, Bzh.z, Bzh.w);
            mma16(Ein, h0A, Bin.x, Bin.y); mma16(Ein, h0A + 4, Bin.z, Bin.w);
            mma16(Ehn, h1A, Bhn.x, Bhn.y); mma16(Ehn, h1A + 4, Bhn.z, Bhn.w);
        }

        float y0 = 0.0f, y1 = 0.0f;
#pragma unroll
        for (int c = 0; c < 2; c++) {
            const float4 C = cB1r[c];
            const float w = cB0r[c].w;
#pragma unroll
            for (int rr = 0; rr < 2; rr++) {
                const int di = rr * 2 + c;
                float r = sig_t(Er[di] + C.x);
                float z = sig_t(Ez[di] + C.y);
                float n = tanh_ap(Ein[di] + C.z + r * (Ehn[di] + C.w));
                float hold = h1D[di];
                float hn = n + z * (hold - n);
                h1D[di] = hn;
                if (rr) y1 = fmaf(hn, w, y1); else y0 = fmaf(hn, w, y0);
            }
        }
        STORE_H(h1D, hx1n);          // consumed after NEXT step's barrier
        y0 += __shfl_xor_sync(0xffffffffu, y0, 1);
        y0 += __shfl_xor_sync(0xffffffffu, y0, 2);
        y1 += __shfl_xor_sync(0xffffffffu, y1, 1);
        y1 += __shfl_xor_sync(0xffffffffu, y1, 2);
        if (tg == 0) {
            yPw[q * 16 + g]     = y0;
            yPw[q * 16 + g + 8] = y1;
        }
        xc0 = xn0;
        xc8 = xn8;
    }

    // drain: y for the last step (partials in buf (SEQ&1)^1... = buf0)
    BARP();
    if (q == 0 && tg == 0) {
        float* yPf = yPbase + ((SEQ & 1) ^ 0) * 0 + ((SEQ - 1 + 1) & 1) * 256; // buf 0
        out[(size_t)(SEQ - 1) * BATCH + base + g] =
            yPf[g] + yPf[16 + g] + yPf[32 + g] + yPf[48 + g] + bo;
        out[(size_t)(SEQ - 1) * BATCH + base + g + 8] =
            yPf[g + 8] + yPf[16 + g + 8] + yPf[32 + g + 8] + yPf[48 + g + 8] + bo;
    }

    // final h_state (2, B, 32)
    float* hout = out + (size_t)SEQ * BATCH;
#pragma unroll
    for (int rr = 0; rr < 2; rr++) {
        size_t r0 = (size_t)(base + g + 8 * rr) * 32 + colb + 2 * tg;
        *(float2*)&hout[r0] = make_float2(h0D[rr * 2], h0D[rr * 2 + 1]);
        *(float2*)&hout[(size_t)BATCH * 32 + r0] = make_float2(h1D[rr * 2], h1D[rr * 2 + 1]);
    }
#undef BARP
#undef STORE_H
#undef LOAD_A
}

extern "C" void kernel_launch(void* const* d_in, const int* in_sizes, int n_in,
                              void* d_out, int out_size) {
    (void)in_sizes; (void)n_in; (void)out_size;
    const float* x    = (const float*)d_in[0];
    const float* h    = (const float*)d_in[1];
    const float* Wih0 = (const float*)d_in[2];
    const float* Whh0 = (const float*)d_in[3];
    const float* bih0 = (const float*)d_in[4];
    const float* bhh0 = (const float*)d_in[5];
    const float* Wih1 = (const float*)d_in[6];
    const float* Whh1 = (const float*)d_in[7];
    const float* bih1 = (const float*)d_in[8];
    const float* bhh1 = (const float*)d_in[9];
    const float* Wout = (const float*)d_in[10];
    const float* bout = (const float*)d_in[11];

    gru2_hmma5_kernel<<<128, 512>>>(x, h, Wih0, Whh0, bih0, bhh0,
                                    Wih1, Whh1, bih1, bhh1, Wout, bout,
                                    (float*)d_out);
}

// round 10
// speedup vs baseline: 1.3219x; 1.3219x over previous
#include <cuda_runtime.h>
#include <cuda_fp16.h>
#include <cstdint>

#define SEQ   256
#define BATCH 8192

// pack two f32 -> f16x2 (lo = first arg)
__device__ __forceinline__ uint32_t pkh(float lo, float hi) {
    uint32_t u; asm("cvt.rn.f16x2.f32 %0, %2, %1;" : "=r"(u) : "f"(lo), "f"(hi)); return u;
}
__device__ __forceinline__ float2 up2(uint32_t u) {
    __half2 h = *reinterpret_cast<__half2*>(&u);
    return __half22float2(h);
}
// 8x8 f16 in-warp transpose
__device__ __forceinline__ uint32_t movm(uint32_t s) {
    uint32_t d;
    asm("movmatrix.sync.aligned.m8n8.trans.b16 %0, %1;" : "=r"(d) : "r"(s));
    return d;
}
// D += A*B
__device__ __forceinline__ void mma16(float d[4], const uint32_t a[4],
                                      uint32_t b0, uint32_t b1) {
    asm("mma.sync.aligned.m16n8k16.row.col.f32.f16.f16.f32 "
        "{%0,%1,%2,%3},{%4,%5,%6,%7},{%8,%9},{%0,%1,%2,%3};"
        : "+f"(d[0]), "+f"(d[1]), "+f"(d[2]), "+f"(d[3])
        : "r"(a[0]), "r"(a[1]), "r"(a[2]), "r"(a[3]), "r"(b0), "r"(b1));
}
// D = A*B + C (fresh accumulator, C = zeros reg set)
__device__ __forceinline__ void mma16o(float d[4], const uint32_t a[4],
                                       uint32_t b0, uint32_t b1, const float c[4]) {
    asm("mma.sync.aligned.m16n8k16.row.col.f32.f16.f16.f32 "
        "{%0,%1,%2,%3},{%4,%5,%6,%7},{%8,%9},{%10,%11,%12,%13};"
        : "=f"(d[0]), "=f"(d[1]), "=f"(d[2]), "=f"(d[3])
        : "r"(a[0]), "r"(a[1]), "r"(a[2]), "r"(a[3]), "r"(b0), "r"(b1),
          "f"(c[0]), "f"(c[1]), "f"(c[2]), "f"(c[3]));
}
// packed tanh on two f32 inputs
__device__ __forceinline__ uint32_t tanh2pk(float a, float b) {
    uint32_t p = pkh(a, b), t;
    asm("tanh.approx.f16x2 %0, %1;" : "=r"(t) : "r"(p));
    return t;
}
// packed sigmoid; inputs PRE-HALVED: sig(x) = 0.5*tanh(x/2)+0.5
__device__ __forceinline__ uint32_t sig2pk(float ah, float bh) {
    uint32_t t = tanh2pk(ah, bh), r;
    const uint32_t H = 0x38003800u;   // (0.5, 0.5) f16x2
    asm("fma.rn.f16x2 %0, %1, %2, %2;" : "=r"(r) : "r"(t), "r"(H));
    return r;
}

// Grid: 148 blocks x 224 threads (7 warps). Warp-unit W = wid*148 + bid,
// active iff W < 1024; warp privately owns 8 batch columns [8W, 8W+8).
// GEMM orientation: D[hidden(m), batch(n)] = W[hidden, k] @ h[k, batch].
// Lane: g = lane>>2, tg = lane&3.
//   D-frag: c0=(unit g, b 2tg), c1=(g, 2tg+1), c2=(g+8, 2tg), c3=(g+8, 2tg+1)
//   B-frag (k=hidden, n=batch) built from D via pkh+movmatrix — NO smem, NO barriers.
__global__ void __launch_bounds__(224, 1) gru2_wp_kernel(
    const float* __restrict__ x,
    const float* __restrict__ h_in,
    const float* __restrict__ Wih0,
    const float* __restrict__ Whh0,
    const float* __restrict__ bih0,
    const float* __restrict__ bhh0,
    const float* __restrict__ Wih1,
    const float* __restrict__ Whh1,
    const float* __restrict__ bih1,
    const float* __restrict__ bhh1,
    const float* __restrict__ Wout,
    const float* __restrict__ bout,
    float* __restrict__ out)
{
    __shared__ float4 KA[32];   // (0.5*Wih0_r, 0.5*Wih0_z, Wih0_n, bih0_n)
    __shared__ float4 KB[32];   // (0.5*(bi_r+bh_r)0, 0.5*(bi_z+bh_z)0, bhh0_n, Wout)
    __shared__ float4 KC[32];   // (0.5*(bi_r+bh_r)1, 0.5*(bi_z+bh_z)1, bih1_n, bhh1_n)
    __shared__ float  boS;

    const int tid = threadIdx.x;
    if (tid < 32) {
        int u = tid;
        KA[u] = make_float4(0.5f * Wih0[u], 0.5f * Wih0[32 + u], Wih0[64 + u], bih0[64 + u]);
        KB[u] = make_float4(0.5f * (bih0[u] + bhh0[u]),
                            0.5f * (bih0[32 + u] + bhh0[32 + u]), bhh0[64 + u], Wout[u]);
        KC[u] = make_float4(0.5f * (bih1[u] + bhh1[u]),
                            0.5f * (bih1[32 + u] + bhh1[32 + u]), bih1[64 + u], bhh1[64 + u]);
    }
    if (tid == 0) boS = bout[0];
    __syncthreads();

    const int wid  = tid >> 5;
    const int lane = tid & 31;
    const int W = wid * 148 + blockIdx.x;
    if (W >= 1024) return;

    const int g  = lane >> 2;
    const int tg = lane & 3;
    const int base = W * 8;
    const float bo = boS;

    // ---- weight A-fragments, register-resident (36 tiles x 4 regs) ----
    // tile (gate, mt, kt): rows gate*32+16mt.., cols 16kt..
    uint32_t W0[3][2][2][4], Wi[3][2][2][4], Wh[3][2][2][4];
#pragma unroll
    for (int gate = 0; gate < 3; gate++)
#pragma unroll
        for (int mt = 0; mt < 2; mt++)
#pragma unroll
            for (int kt = 0; kt < 2; kt++)
#pragma unroll
                for (int aa = 0; aa < 4; aa++) {
                    int row = gate * 32 + mt * 16 + g + (aa & 1) * 8;
                    int col = kt * 16 + 2 * tg + (aa >> 1) * 8;
                    float2 v0 = *(const float2*)&Whh0[row * 32 + col];
                    float2 vi = *(const float2*)&Wih1[row * 32 + col];
                    float2 vh = *(const float2*)&Whh1[row * 32 + col];
                    W0[gate][mt][kt][aa] = pkh(v0.x, v0.y);
                    Wi[gate][mt][kt][aa] = pkh(vi.x, vi.y);
                    Wh[gate][mt][kt][aa] = pkh(vh.x, vh.y);
                }

    const float z4[4] = {0.0f, 0.0f, 0.0f, 0.0f};

    // ---- h masters (f32, D-layout) ----
    float h0D[2][4], h1D[2][4];
#pragma unroll
    for (int mt = 0; mt < 2; mt++)
#pragma unroll
        for (int rr = 0; rr < 2; rr++)
#pragma unroll
            for (int c = 0; c < 2; c++) {
                int u = 16 * mt + 8 * rr + g;
                int b = base + 2 * tg + c;
                h0D[mt][rr * 2 + c] = h_in[(size_t)b * 32 + u];
                h1D[mt][rr * 2 + c] = h_in[(size_t)(BATCH + b) * 32 + u];
            }

    // ---- B-fragments via transpose ----
    uint32_t hB0[4], hB1[4];
#pragma unroll
    for (int mt = 0; mt < 2; mt++) {
        hB0[mt * 2]     = movm(pkh(h0D[mt][0], h0D[mt][1]));
        hB0[mt * 2 + 1] = movm(pkh(h0D[mt][2], h0D[mt][3]));
        hB1[mt * 2]     = movm(pkh(h1D[mt][0], h1D[mt][1]));
        hB1[mt * 2 + 1] = movm(pkh(h1D[mt][2], h1D[mt][3]));
    }

    float2 xv = *(const float2*)&x[base + 2 * tg];

    for (int st = 0; st < SEQ; st++) {
        float2 xn = *(const float2*)&x[(size_t)min(st + 1, SEQ - 1) * BATCH + base + 2 * tg];

        // ---------- layer 0: 12 MMAs ----------
        float Dr[2][4], Dz[2][4], Dn[2][4];
#pragma unroll
        for (int mt = 0; mt < 2; mt++) {
            mma16o(Dr[mt], W0[0][mt][0], hB0[0], hB0[1], z4);
            mma16 (Dr[mt], W0[0][mt][1], hB0[2], hB0[3]);
            mma16o(Dz[mt], W0[1][mt][0], hB0[0], hB0[1], z4);
            mma16 (Dz[mt], W0[1][mt][1], hB0[2], hB0[3]);
            mma16o(Dn[mt], W0[2][mt][0], hB0[0], hB0[1], z4);
            mma16 (Dn[mt], W0[2][mt][1], hB0[2], hB0[3]);
        }
        // ---------- layer 0 epilogue ----------
#pragma unroll
        for (int mt = 0; mt < 2; mt++)
#pragma unroll
            for (int rr = 0; rr < 2; rr++) {
                const int u = 16 * mt + 8 * rr + g;
                const float4 A  = KA[u];
                const float4 Bc = KB[u];
                const int d0 = rr * 2, d1 = rr * 2 + 1;
                float pr0 = fmaf(xv.x, A.x, fmaf(Dr[mt][d0], 0.5f, Bc.x));
                float pr1 = fmaf(xv.y, A.x, fmaf(Dr[mt][d1], 0.5f, Bc.x));
                float pz0 = fmaf(xv.x, A.y, fmaf(Dz[mt][d0], 0.5f, Bc.y));
                float pz1 = fmaf(xv.y, A.y, fmaf(Dz[mt][d1], 0.5f, Bc.y));
                float2 rf = up2(sig2pk(pr0, pr1));
                float2 zf = up2(sig2pk(pz0, pz1));
                float pn0 = fmaf(rf.x, Dn[mt][d0] + Bc.z, fmaf(xv.x, A.z, A.w));
                float pn1 = fmaf(rf.y, Dn[mt][d1] + Bc.z, fmaf(xv.y, A.z, A.w));
                float2 nf = up2(tanh2pk(pn0, pn1));
                float o0 = h0D[mt][d0], o1 = h0D[mt][d1];
                h0D[mt][d0] = nf.x + zf.x * (o0 - nf.x);
                h0D[mt][d1] = nf.y + zf.y * (o1 - nf.y);
            }
        // h0' -> B-frags (in-warp transpose)
#pragma unroll
        for (int mt = 0; mt < 2; mt++) {
            hB0[mt * 2]     = movm(pkh(h0D[mt][0], h0D[mt][1]));
            hB0[mt * 2 + 1] = movm(pkh(h0D[mt][2], h0D[mt][3]));
        }

        // ---------- layer 1: 24 MMAs ----------
        float Er[2][4], Ez[2][4], Ei[2][4], Eh[2][4];
#pragma unroll
        for (int mt = 0; mt < 2; mt++) {
            mma16o(Er[mt], Wi[0][mt][0], hB0[0], hB0[1], z4);
            mma16 (Er[mt], Wi[0][mt][1], hB0[2], hB0[3]);
            mma16 (Er[mt], Wh[0][mt][0], hB1[0], hB1[1]);
            mma16 (Er[mt], Wh[0][mt][1], hB1[2], hB1[3]);
            mma16o(Ez[mt], Wi[1][mt][0], hB0[0], hB0[1], z4);
            mma16 (Ez[mt], Wi[1][mt][1], hB0[2], hB0[3]);
            mma16 (Ez[mt], Wh[1][mt][0], hB1[0], hB1[1]);
            mma16 (Ez[mt], Wh[1][mt][1], hB1[2], hB1[3]);
            mma16o(Ei[mt], Wi[2][mt][0], hB0[0], hB0[1], z4);
            mma16 (Ei[mt], Wi[2][mt][1], hB0[2], hB0[3]);
            mma16o(Eh[mt], Wh[2][mt][0], hB1[0], hB1[1], z4);
            mma16 (Eh[mt], Wh[2][mt][1], hB1[2], hB1[3]);
        }
        // ---------- layer 1 epilogue + y ----------
        float y0 = 0.0f, y1 = 0.0f;
#pragma unroll
        for (int mt = 0; mt < 2; mt++)
#pragma unroll
            for (int rr = 0; rr < 2; rr++) {
                const int u = 16 * mt + 8 * rr + g;
                const float4 C = KC[u];
                const float wou = KB[u].w;
                const int d0 = rr * 2, d1 = rr * 2 + 1;
                float pr0 = fmaf(Er[mt][d0], 0.5f, C.x);
                float pr1 = fmaf(Er[mt][d1], 0.5f, C.x);
                float pz0 = fmaf(Ez[mt][d0], 0.5f, C.y);
                float pz1 = fmaf(Ez[mt][d1], 0.5f, C.y);
                float2 rf = up2(sig2pk(pr0, pr1));
                float2 zf = up2(sig2pk(pz0, pz1));
                float pn0 = fmaf(rf.x, Eh[mt][d0] + C.w, Ei[mt][d0] + C.z);
                float pn1 = fmaf(rf.y, Eh[mt][d1] + C.w, Ei[mt][d1] + C.z);
                float2 nf = up2(tanh2pk(pn0, pn1));
                float o0 = h1D[mt][d0], o1 = h1D[mt][d1];
                float hn0 = nf.x + zf.x * (o0 - nf.x);
                float hn1 = nf.y + zf.y * (o1 - nf.y);
                h1D[mt][d0] = hn0;
                h1D[mt][d1] = hn1;
                y0 = fmaf(hn0, wou, y0);
                y1 = fmaf(hn1, wou, y1);
            }
        // h1' -> B-frags
#pragma unroll
        for (int mt = 0; mt < 2; mt++) {
            hB1[mt * 2]     = movm(pkh(h1D[mt][0], h1D[mt][1]));
            hB1[mt * 2 + 1] = movm(pkh(h1D[mt][2], h1D[mt][3]));
        }

        // y reduce over g (lane bits 2,3,4) and store
        y0 += __shfl_xor_sync(0xffffffffu, y0, 4);
        y0 += __shfl_xor_sync(0xffffffffu, y0, 8);
        y0 += __shfl_xor_sync(0xffffffffu, y0, 16);
        y1 += __shfl_xor_sync(0xffffffffu, y1, 4);
        y1 += __shfl_xor_sync(0xffffffffu, y1, 8);
        y1 += __shfl_xor_sync(0xffffffffu, y1, 16);
        if (lane < 4) {
            float2 yo = make_float2(y0 + bo, y1 + bo);
            *(float2*)&out[(size_t)st * BATCH + base + 2 * tg] = yo;
        }
        xv = xn;
    }

    // final h_state (2, B, 32)
    float* hout = out + (size_t)SEQ * BATCH;
#pragma unroll
    for (int mt = 0; mt < 2; mt++)
#pragma unroll
        for (int rr = 0; rr < 2; rr++)
#pragma unroll
            for (int c = 0; c < 2; c++) {
                int u = 16 * mt + 8 * rr + g;
                int b = base + 2 * tg + c;
                hout[(size_t)b * 32 + u] = h0D[mt][rr * 2 + c];
                hout[(size_t)(BATCH + b) * 32 + u] = h1D[mt][rr * 2 + c];
            }
}

extern "C" void kernel_launch(void* const* d_in, const int* in_sizes, int n_in,
                              void* d_out, int out_size) {
    (void)in_sizes; (void)n_in; (void)out_size;
    const float* x    = (const float*)d_in[0];
    const float* h    = (const float*)d_in[1];
    const float* Wih0 = (const float*)d_in[2];
    const float* Whh0 = (const float*)d_in[3];
    const float* bih0 = (const float*)d_in[4];
    const float* bhh0 = (const float*)d_in[5];
    const float* Wih1 = (const float*)d_in[6];
    const float* Whh1 = (const float*)d_in[7];
    const float* bih1 = (const float*)d_in[8];
    const float* bhh1 = (const float*)d_in[9];
    const float* Wout = (const float*)d_in[10];
    const float* bout = (const float*)d_in[11];

    // 148 blocks x 7 warps: 1024 warp-units x 8 batch = 8192; barrier-free loop
    gru2_wp_kernel<<<148, 224>>>(x, h, Wih0, Whh0, bih0, bhh0,
                                 Wih1, Whh1, bih1, bhh1, Wout, bout,
                                 (float*)d_out);
}

// round 11
// speedup vs baseline: 1.4420x; 1.0909x over previous
#include <cuda_runtime.h>
#include <cuda_fp16.h>
#include <cstdint>

#define SEQ   256
#define BATCH 8192

// pack two f32 -> f16x2 (lo = first arg)
__device__ __forceinline__ uint32_t pkh(float lo, float hi) {
    uint32_t u; asm("cvt.rn.f16x2.f32 %0, %2, %1;" : "=r"(u) : "f"(lo), "f"(hi)); return u;
}
// 8x8 f16 in-warp transpose
__device__ __forceinline__ uint32_t movm(uint32_t s) {
    uint32_t d;
    asm("movmatrix.sync.aligned.m8n8.trans.b16 %0, %1;" : "=r"(d) : "r"(s));
    return d;
}
// D += A*B
__device__ __forceinline__ void mma16(float d[4], const uint32_t a[4],
                                      uint32_t b0, uint32_t b1) {
    asm("mma.sync.aligned.m16n8k16.row.col.f32.f16.f16.f32 "
        "{%0,%1,%2,%3},{%4,%5,%6,%7},{%8,%9},{%0,%1,%2,%3};"
        : "+f"(d[0]), "+f"(d[1]), "+f"(d[2]), "+f"(d[3])
        : "r"(a[0]), "r"(a[1]), "r"(a[2]), "r"(a[3]), "r"(b0), "r"(b1));
}
// D = A*B (fresh accumulator)
__device__ __forceinline__ void mma16o(float d[4], const uint32_t a[4],
                                       uint32_t b0, uint32_t b1) {
    asm("mma.sync.aligned.m16n8k16.row.col.f32.f16.f16.f32 "
        "{%0,%1,%2,%3},{%4,%5,%6,%7},{%8,%9},{%10,%10,%10,%10};"
        : "=f"(d[0]), "=f"(d[1]), "=f"(d[2]), "=f"(d[3])
        : "r"(a[0]), "r"(a[1]), "r"(a[2]), "r"(a[3]), "r"(b0), "r"(b1),
          "f"(0.0f));
}
// f32 gates (R8-identical math): sigmoid(x) = 0.5*tanh(0.5x)+0.5
__device__ __forceinline__ float sig_t(float x) {
    float t; asm("tanh.approx.f32 %0, %1;" : "=f"(t) : "f"(0.5f * x));
    return fmaf(t, 0.5f, 0.5f);
}
__device__ __forceinline__ float tanh_ap(float x) {
    float t; asm("tanh.approx.f32 %0, %1;" : "=f"(t) : "f"(x)); return t;
}

// Grid: 148 blocks x 224 threads (7 warps). Warp-unit W = wid*148 + bid,
// active iff W < 1024; warp privately owns 8 batch columns [8W, 8W+8).
// GEMM orientation: D[hidden(m), batch(n)] = W[hidden, k] @ h[k, batch].
// Lane: g = lane>>2, tg = lane&3.
//   D-frag: c0=(unit g, b 2tg), c1=(g, 2tg+1), c2=(g+8, 2tg), c3=(g+8, 2tg+1)
//   B-frag built from D via pkh+movmatrix — no smem, no barriers in the loop.
__global__ void __launch_bounds__(224, 1) gru2_wp2_kernel(
    const float* __restrict__ x,
    const float* __restrict__ h_in,
    const float* __restrict__ Wih0,
    const float* __restrict__ Whh0,
    const float* __restrict__ bih0,
    const float* __restrict__ bhh0,
    const float* __restrict__ Wih1,
    const float* __restrict__ Whh1,
    const float* __restrict__ bih1,
    const float* __restrict__ bhh1,
    const float* __restrict__ Wout,
    const float* __restrict__ bout,
    float* __restrict__ out)
{
    __shared__ float4 KA[32];   // (Wih0_r, Wih0_z, Wih0_n, bih0_n)
    __shared__ float4 KB[32];   // (br0c, bz0c, bhn0, Wout)
    __shared__ float4 KC[32];   // (br1c, bz1c, bin1, bhn1)
    __shared__ float  boS;

    const int tid = threadIdx.x;
    if (tid < 32) {
        int u = tid;
        KA[u] = make_float4(Wih0[u], Wih0[32 + u], Wih0[64 + u], bih0[64 + u]);
        KB[u] = make_float4(bih0[u] + bhh0[u], bih0[32 + u] + bhh0[32 + u],
                            bhh0[64 + u], Wout[u]);
        KC[u] = make_float4(bih1[u] + bhh1[u], bih1[32 + u] + bhh1[32 + u],
                            bih1[64 + u], bhh1[64 + u]);
    }
    if (tid == 0) boS = bout[0];
    __syncthreads();

    const int wid  = tid >> 5;
    const int lane = tid & 31;
    const int W = wid * 148 + blockIdx.x;
    if (W >= 1024) return;

    const int g  = lane >> 2;
    const int tg = lane & 3;
    const int base = W * 8;
    const float bo = boS;

    // ---- weight A-fragments, register-resident (36 tiles x 4 regs) ----
    uint32_t W0[3][2][2][4], Wi[3][2][2][4], Wh[3][2][2][4];
#pragma unroll
    for (int gate = 0; gate < 3; gate++)
#pragma unroll
        for (int mt = 0; mt < 2; mt++)
#pragma unroll
            for (int kt = 0; kt < 2; kt++)
#pragma unroll
                for (int aa = 0; aa < 4; aa++) {
                    int row = gate * 32 + mt * 16 + g + (aa & 1) * 8;
                    int col = kt * 16 + 2 * tg + (aa >> 1) * 8;
                    float2 v0 = *(const float2*)&Whh0[row * 32 + col];
                    float2 vi = *(const float2*)&Wih1[row * 32 + col];
                    float2 vh = *(const float2*)&Whh1[row * 32 + col];
                    W0[gate][mt][kt][aa] = pkh(v0.x, v0.y);
                    Wi[gate][mt][kt][aa] = pkh(vi.x, vi.y);
                    Wh[gate][mt][kt][aa] = pkh(vh.x, vh.y);
                }

    // ---- h masters (f32, D-layout) ----
    float h0D[2][4], h1D[2][4];
#pragma unroll
    for (int mt = 0; mt < 2; mt++)
#pragma unroll
        for (int rr = 0; rr < 2; rr++)
#pragma unroll
            for (int c = 0; c < 2; c++) {
                int u = 16 * mt + 8 * rr + g;
                int b = base + 2 * tg + c;
                h0D[mt][rr * 2 + c] = h_in[(size_t)b * 32 + u];
                h1D[mt][rr * 2 + c] = h_in[(size_t)(BATCH + b) * 32 + u];
            }

    // ---- B-fragments via transpose ----
    uint32_t hB0[4], hB1[4];
#pragma unroll
    for (int mt = 0; mt < 2; mt++) {
        hB0[mt * 2]     = movm(pkh(h0D[mt][0], h0D[mt][1]));
        hB0[mt * 2 + 1] = movm(pkh(h0D[mt][2], h0D[mt][3]));
        hB1[mt * 2]     = movm(pkh(h1D[mt][0], h1D[mt][1]));
        hB1[mt * 2 + 1] = movm(pkh(h1D[mt][2], h1D[mt][3]));
    }

    float2 xv = *(const float2*)&x[base + 2 * tg];

    for (int st = 0; st < SEQ; st++) {
        float2 xn = *(const float2*)&x[(size_t)min(st + 1, SEQ - 1) * BATCH + base + 2 * tg];

        // ---------- layer 0: per-mt MMA + epilogue (low accumulator liveness) ----------
#pragma unroll
        for (int mt = 0; mt < 2; mt++) {
            float Dr[4], Dz[4], Dn[4];
            mma16o(Dr, W0[0][mt][0], hB0[0], hB0[1]);
            mma16 (Dr, W0[0][mt][1], hB0[2], hB0[3]);
            mma16o(Dz, W0[1][mt][0], hB0[0], hB0[1]);
            mma16 (Dz, W0[1][mt][1], hB0[2], hB0[3]);
            mma16o(Dn, W0[2][mt][0], hB0[0], hB0[1]);
            mma16 (Dn, W0[2][mt][1], hB0[2], hB0[3]);
#pragma unroll
            for (int rr = 0; rr < 2; rr++) {
                const int u = 16 * mt + 8 * rr + g;
                const float4 A  = KA[u];
                const float4 Bc = KB[u];
#pragma unroll
                for (int c = 0; c < 2; c++) {
                    const int di = rr * 2 + c;
                    const float xvc = c ? xv.y : xv.x;
                    float r = sig_t(fmaf(xvc, A.x, Dr[di] + Bc.x));
                    float z = sig_t(fmaf(xvc, A.y, Dz[di] + Bc.y));
                    float n = tanh_ap(fmaf(xvc, A.z, A.w) + r * (Dn[di] + Bc.z));
                    float hold = h0D[mt][di];
                    h0D[mt][di] = n + z * (hold - n);
                }
            }
        }
        // h0' -> B-frags (in-warp transpose)
#pragma unroll
        for (int mt = 0; mt < 2; mt++) {
            hB0[mt * 2]     = movm(pkh(h0D[mt][0], h0D[mt][1]));
            hB0[mt * 2 + 1] = movm(pkh(h0D[mt][2], h0D[mt][3]));
        }

        // ---------- layer 1: per-mt MMA + epilogue ----------
        float y0 = 0.0f, y1 = 0.0f;
#pragma unroll
        for (int mt = 0; mt < 2; mt++) {
            float Er[4], Ez[4], Ei[4], Eh[4];
            mma16o(Er, Wi[0][mt][0], hB0[0], hB0[1]);
            mma16 (Er, Wi[0][mt][1], hB0[2], hB0[3]);
            mma16 (Er, Wh[0][mt][0], hB1[0], hB1[1]);
            mma16 (Er, Wh[0][mt][1], hB1[2], hB1[3]);
            mma16o(Ez, Wi[1][mt][0], hB0[0], hB0[1]);
            mma16 (Ez, Wi[1][mt][1], hB0[2], hB0[3]);
            mma16 (Ez, Wh[1][mt][0], hB1[0], hB1[1]);
            mma16 (Ez, Wh[1][mt][1], hB1[2], hB1[3]);
            mma16o(Ei, Wi[2][mt][0], hB0[0], hB0[1]);
            mma16 (Ei, Wi[2][mt][1], hB0[2], hB0[3]);
            mma16o(Eh, Wh[2][mt][0], hB1[0], hB1[1]);
            mma16 (Eh, Wh[2][mt][1], hB1[2], hB1[3]);
#pragma unroll
            for (int rr = 0; rr < 2; rr++) {
                const int u = 16 * mt + 8 * rr + g;
                const float4 C = KC[u];
                const float wou = KB[u].w;
#pragma unroll
                for (int c = 0; c < 2; c++) {
                    const int di = rr * 2 + c;
                    float r = sig_t(Er[di] + C.x);
                    float z = sig_t(Ez[di] + C.y);
                    float n = tanh_ap(Ei[di] + C.z + r * (Eh[di] + C.w));
                    float hold = h1D[mt][di];
                    float hn = n + z * (hold - n);
                    h1D[mt][di] = hn;
                    if (c) y1 = fmaf(hn, wou, y1); else y0 = fmaf(hn, wou, y0);
                }
            }
        }
        // h1' -> B-frags
#pragma unroll
        for (int mt = 0; mt < 2; mt++) {
            hB1[mt * 2]     = movm(pkh(h1D[mt][0], h1D[mt][1]));
            hB1[mt * 2 + 1] = movm(pkh(h1D[mt][2], h1D[mt][3]));
        }

        // y reduce over g (lane bits 2,3,4) and store
        y0 += __shfl_xor_sync(0xffffffffu, y0, 4);
        y0 += __shfl_xor_sync(0xffffffffu, y0, 8);
        y0 += __shfl_xor_sync(0xffffffffu, y0, 16);
        y1 += __shfl_xor_sync(0xffffffffu, y1, 4);
        y1 += __shfl_xor_sync(0xffffffffu, y1, 8);
        y1 += __shfl_xor_sync(0xffffffffu, y1, 16);
        if (lane < 4) {
            float2 yo = make_float2(y0 + bo, y1 + bo);
            *(float2*)&out[(size_t)st * BATCH + base + 2 * tg] = yo;
        }
        xv = xn;
    }

    // final h_state (2, B, 32)
    float* hout = out + (size_t)SEQ * BATCH;
#pragma unroll
    for (int mt = 0; mt < 2; mt++)
#pragma unroll
        for (int rr = 0; rr < 2; rr++)
#pragma unroll
            for (int c = 0; c < 2; c++) {
                int u = 16 * mt + 8 * rr + g;
                int b = base + 2 * tg + c;
                hout[(size_t)b * 32 + u] = h0D[mt][rr * 2 + c];
                hout[(size_t)(BATCH + b) * 32 + u] = h1D[mt][rr * 2 + c];
            }
}

extern "C" void kernel_launch(void* const* d_in, const int* in_sizes, int n_in,
                              void* d_out, int out_size) {
    (void)in_sizes; (void)n_in; (void)out_size;
    const float* x    = (const float*)d_in[0];
    const float* h    = (const float*)d_in[1];
    const float* Wih0 = (const float*)d_in[2];
    const float* Whh0 = (const float*)d_in[3];
    const float* bih0 = (const float*)d_in[4];
    const float* bhh0 = (const float*)d_in[5];
    const float* Wih1 = (const float*)d_in[6];
    const float* Whh1 = (const float*)d_in[7];
    const float* bih1 = (const float*)d_in[8];
    const float* bhh1 = (const float*)d_in[9];
    const float* Wout = (const float*)d_in[10];
    const float* bout = (const float*)d_in[11];

    // 148 blocks x 7 warps: 1024 warp-units x 8 batch = 8192; barrier-free loop
    gru2_wp2_kernel<<<148, 224>>>(x, h, Wih0, Whh0, bih0, bhh0,
                                  Wih1, Whh1, bih1, bhh1, Wout, bout,
                                  (float*)d_out);
}

// round 12
// speedup vs baseline: 1.5218x; 1.0553x over previous
#include <cuda_runtime.h>
#include <cuda_fp16.h>
#include <cstdint>

#define SEQ   256
#define BATCH 8192

// pack two f32 -> f16x2 (lo = first arg)
__device__ __forceinline__ uint32_t pkh(float lo, float hi) {
    uint32_t u; asm("cvt.rn.f16x2.f32 %0, %2, %1;" : "=r"(u) : "f"(lo), "f"(hi)); return u;
}
// 8x8 f16 in-warp transpose
__device__ __forceinline__ uint32_t movm(uint32_t s) {
    uint32_t d;
    asm("movmatrix.sync.aligned.m8n8.trans.b16 %0, %1;" : "=r"(d) : "r"(s));
    return d;
}
// D += A*B
__device__ __forceinline__ void mma16(float d[4], const uint32_t a[4],
                                      uint32_t b0, uint32_t b1) {
    asm("mma.sync.aligned.m16n8k16.row.col.f32.f16.f16.f32 "
        "{%0,%1,%2,%3},{%4,%5,%6,%7},{%8,%9},{%0,%1,%2,%3};"
        : "+f"(d[0]), "+f"(d[1]), "+f"(d[2]), "+f"(d[3])
        : "r"(a[0]), "r"(a[1]), "r"(a[2]), "r"(a[3]), "r"(b0), "r"(b1));
}
// D = A*B (fresh accumulator)
__device__ __forceinline__ void mma16o(float d[4], const uint32_t a[4],
                                       uint32_t b0, uint32_t b1) {
    asm("mma.sync.aligned.m16n8k16.row.col.f32.f16.f16.f32 "
        "{%0,%1,%2,%3},{%4,%5,%6,%7},{%8,%9},{%10,%10,%10,%10};"
        : "=f"(d[0]), "=f"(d[1]), "=f"(d[2]), "=f"(d[3])
        : "r"(a[0]), "r"(a[1]), "r"(a[2]), "r"(a[3]), "r"(b0), "r"(b1),
          "f"(0.0f));
}
// f32 gates: sigmoid(x) = 0.5*tanh(0.5x)+0.5
__device__ __forceinline__ float sig_t(float x) {
    float t; asm("tanh.approx.f32 %0, %1;" : "=f"(t) : "f"(0.5f * x));
    return fmaf(t, 0.5f, 0.5f);
}
__device__ __forceinline__ float tanh_ap(float x) {
    float t; asm("tanh.approx.f32 %0, %1;" : "=f"(t) : "f"(x)); return t;
}

// Grid: 148 blocks x 224 threads (7 warps). Warp-unit W = wid*148 + bid,
// active iff W < 1024; warp privately owns 8 batch columns [8W, 8W+8).
// D[hidden(m), batch(n)] = W[hidden,k] @ h[k,batch]; movmatrix recurrence,
// no smem exchange, no barriers in the loop.
// NEW: Wh x hB1 MMAs hoisted to step top — overlap with the whole L0 chain.
__global__ void __launch_bounds__(224, 1) gru2_wp3_kernel(
    const float* __restrict__ x,
    const float* __restrict__ h_in,
    const float* __restrict__ Wih0,
    const float* __restrict__ Whh0,
    const float* __restrict__ bih0,
    const float* __restrict__ bhh0,
    const float* __restrict__ Wih1,
    const float* __restrict__ Whh1,
    const float* __restrict__ bih1,
    const float* __restrict__ bhh1,
    const float* __restrict__ Wout,
    const float* __restrict__ bout,
    float* __restrict__ out)
{
    __shared__ float4 KA[32];   // (Wih0_r, Wih0_z, Wih0_n, bih0_n)
    __shared__ float4 KB[32];   // (br0c, bz0c, bhn0, Wout)
    __shared__ float4 KC[32];   // (br1c, bz1c, bin1, bhn1)
    __shared__ float  boS;

    const int tid = threadIdx.x;
    if (tid < 32) {
        int u = tid;
        KA[u] = make_float4(Wih0[u], Wih0[32 + u], Wih0[64 + u], bih0[64 + u]);
        KB[u] = make_float4(bih0[u] + bhh0[u], bih0[32 + u] + bhh0[32 + u],
                            bhh0[64 + u], Wout[u]);
        KC[u] = make_float4(bih1[u] + bhh1[u], bih1[32 + u] + bhh1[32 + u],
                            bih1[64 + u], bhh1[64 + u]);
    }
    if (tid == 0) boS = bout[0];
    __syncthreads();

    const int wid  = tid >> 5;
    const int lane = tid & 31;
    const int W = wid * 148 + blockIdx.x;
    if (W >= 1024) return;

    const int g  = lane >> 2;
    const int tg = lane & 3;
    const int base = W * 8;
    const float bo = boS;

    // ---- weight A-fragments, register-resident (36 tiles x 4 regs) ----
    uint32_t W0[3][2][2][4], Wi[3][2][2][4], Wh[3][2][2][4];
#pragma unroll
    for (int gate = 0; gate < 3; gate++)
#pragma unroll
        for (int mt = 0; mt < 2; mt++)
#pragma unroll
            for (int kt = 0; kt < 2; kt++)
#pragma unroll
                for (int aa = 0; aa < 4; aa++) {
                    int row = gate * 32 + mt * 16 + g + (aa & 1) * 8;
                    int col = kt * 16 + 2 * tg + (aa >> 1) * 8;
                    float2 v0 = *(const float2*)&Whh0[row * 32 + col];
                    float2 vi = *(const float2*)&Wih1[row * 32 + col];
                    float2 vh = *(const float2*)&Whh1[row * 32 + col];
                    W0[gate][mt][kt][aa] = pkh(v0.x, v0.y);
                    Wi[gate][mt][kt][aa] = pkh(vi.x, vi.y);
                    Wh[gate][mt][kt][aa] = pkh(vh.x, vh.y);
                }

    // ---- h masters (f32, D-layout) ----
    float h0D[2][4], h1D[2][4];
#pragma unroll
    for (int mt = 0; mt < 2; mt++)
#pragma unroll
        for (int rr = 0; rr < 2; rr++)
#pragma unroll
            for (int c = 0; c < 2; c++) {
                int u = 16 * mt + 8 * rr + g;
                int b = base + 2 * tg + c;
                h0D[mt][rr * 2 + c] = h_in[(size_t)b * 32 + u];
                h1D[mt][rr * 2 + c] = h_in[(size_t)(BATCH + b) * 32 + u];
            }

    // ---- B-fragments via transpose ----
    uint32_t hB0[4], hB1[4];
#pragma unroll
    for (int mt = 0; mt < 2; mt++) {
        hB0[mt * 2]     = movm(pkh(h0D[mt][0], h0D[mt][1]));
        hB0[mt * 2 + 1] = movm(pkh(h0D[mt][2], h0D[mt][3]));
        hB1[mt * 2]     = movm(pkh(h1D[mt][0], h1D[mt][1]));
        hB1[mt * 2 + 1] = movm(pkh(h1D[mt][2], h1D[mt][3]));
    }

    float2 xv = *(const float2*)&x[base + 2 * tg];

    for (int st = 0; st < SEQ; st++) {
        float2 xn = *(const float2*)&x[(size_t)min(st + 1, SEQ - 1) * BATCH + base + 2 * tg];

        // ===== HOISTED: L1 Wh x h1 contributions (independent of L0) =====
        float Er[2][4], Ez[2][4], Eh[2][4];
#pragma unroll
        for (int mt = 0; mt < 2; mt++) {
            mma16o(Er[mt], Wh[0][mt][0], hB1[0], hB1[1]);
            mma16 (Er[mt], Wh[0][mt][1], hB1[2], hB1[3]);
            mma16o(Ez[mt], Wh[1][mt][0], hB1[0], hB1[1]);
            mma16 (Ez[mt], Wh[1][mt][1], hB1[2], hB1[3]);
            mma16o(Eh[mt], Wh[2][mt][0], hB1[0], hB1[1]);
            mma16 (Eh[mt], Wh[2][mt][1], hB1[2], hB1[3]);
        }

        // ---------- layer 0: per-mt MMA + epilogue ----------
#pragma unroll
        for (int mt = 0; mt < 2; mt++) {
            float Dr[4], Dz[4], Dn[4];
            mma16o(Dr, W0[0][mt][0], hB0[0], hB0[1]);
            mma16 (Dr, W0[0][mt][1], hB0[2], hB0[3]);
            mma16o(Dz, W0[1][mt][0], hB0[0], hB0[1]);
            mma16 (Dz, W0[1][mt][1], hB0[2], hB0[3]);
            mma16o(Dn, W0[2][mt][0], hB0[0], hB0[1]);
            mma16 (Dn, W0[2][mt][1], hB0[2], hB0[3]);
#pragma unroll
            for (int rr = 0; rr < 2; rr++) {
                const int u = 16 * mt + 8 * rr + g;
                const float4 A  = KA[u];
                const float4 Bc = KB[u];
#pragma unroll
                for (int c = 0; c < 2; c++) {
                    const int di = rr * 2 + c;
                    const float xvc = c ? xv.y : xv.x;
                    float r = sig_t(fmaf(xvc, A.x, Dr[di] + Bc.x));
                    float z = sig_t(fmaf(xvc, A.y, Dz[di] + Bc.y));
                    float n = tanh_ap(fmaf(xvc, A.z, A.w) + r * (Dn[di] + Bc.z));
                    float hold = h0D[mt][di];
                    h0D[mt][di] = n + z * (hold - n);
                }
            }
        }
        // h0' -> B-frags (in-warp transpose)
#pragma unroll
        for (int mt = 0; mt < 2; mt++) {
            hB0[mt * 2]     = movm(pkh(h0D[mt][0], h0D[mt][1]));
            hB0[mt * 2 + 1] = movm(pkh(h0D[mt][2], h0D[mt][3]));
        }

        // ---------- layer 1: Wi x h0' appended, then epilogue ----------
        float y0 = 0.0f, y1 = 0.0f;
#pragma unroll
        for (int mt = 0; mt < 2; mt++) {
            float Ei[4];
            mma16 (Er[mt], Wi[0][mt][0], hB0[0], hB0[1]);
            mma16 (Er[mt], Wi[0][mt][1], hB0[2], hB0[3]);
            mma16 (Ez[mt], Wi[1][mt][0], hB0[0], hB0[1]);
            mma16 (Ez[mt], Wi[1][mt][1], hB0[2], hB0[3]);
            mma16o(Ei,     Wi[2][mt][0], hB0[0], hB0[1]);
            mma16 (Ei,     Wi[2][mt][1], hB0[2], hB0[3]);
#pragma unroll
            for (int rr = 0; rr < 2; rr++) {
                const int u = 16 * mt + 8 * rr + g;
                const float4 C = KC[u];
                const float wou = KB[u].w;
#pragma unroll
                for (int c = 0; c < 2; c++) {
                    const int di = rr * 2 + c;
                    float r = sig_t(Er[mt][di] + C.x);
                    float z = sig_t(Ez[mt][di] + C.y);
                    float n = tanh_ap(Ei[di] + C.z + r * (Eh[mt][di] + C.w));
                    float hold = h1D[mt][di];
                    float hn = n + z * (hold - n);
                    h1D[mt][di] = hn;
                    if (c) y1 = fmaf(hn, wou, y1); else y0 = fmaf(hn, wou, y0);
                }
            }
        }
        // h1' -> B-frags
#pragma unroll
        for (int mt = 0; mt < 2; mt++) {
            hB1[mt * 2]     = movm(pkh(h1D[mt][0], h1D[mt][1]));
            hB1[mt * 2 + 1] = movm(pkh(h1D[mt][2], h1D[mt][3]));
        }

        // y reduce over g (lane bits 2,3,4) and store
        y0 += __shfl_xor_sync(0xffffffffu, y0, 4);
        y0 += __shfl_xor_sync(0xffffffffu, y0, 8);
        y0 += __shfl_xor_sync(0xffffffffu, y0, 16);
        y1 += __shfl_xor_sync(0xffffffffu, y1, 4);
        y1 += __shfl_xor_sync(0xffffffffu, y1, 8);
        y1 += __shfl_xor_sync(0xffffffffu, y1, 16);
        if (lane < 4) {
            float2 yo = make_float2(y0 + bo, y1 + bo);
            *(float2*)&out[(size_t)st * BATCH + base + 2 * tg] = yo;
        }
        xv = xn;
    }

    // final h_state (2, B, 32)
    float* hout = out + (size_t)SEQ * BATCH;
#pragma unroll
    for (int mt = 0; mt < 2; mt++)
#pragma unroll
        for (int rr = 0; rr < 2; rr++)
#pragma unroll
            for (int c = 0; c < 2; c++) {
                int u = 16 * mt + 8 * rr + g;
                int b = base + 2 * tg + c;
                hout[(size_t)b * 32 + u] = h0D[mt][rr * 2 + c];
                hout[(size_t)(BATCH + b) * 32 + u] = h1D[mt][rr * 2 + c];
            }
}

extern "C" void kernel_launch(void* const* d_in, const int* in_sizes, int n_in,
                              void* d_out, int out_size) {
    (void)in_sizes; (void)n_in; (void)out_size;
    const float* x    = (const float*)d_in[0];
    const float* h    = (const float*)d_in[1];
    const float* Wih0 = (const float*)d_in[2];
    const float* Whh0 = (const float*)d_in[3];
    const float* bih0 = (const float*)d_in[4];
    const float* bhh0 = (const float*)d_in[5];
    const float* Wih1 = (const float*)d_in[6];
    const float* Whh1 = (const float*)d_in[7];
    const float* bih1 = (const float*)d_in[8];
    const float* bhh1 = (const float*)d_in[9];
    const float* Wout = (const float*)d_in[10];
    const float* bout = (const float*)d_in[11];

    // 148 blocks x 7 warps: 1024 warp-units x 8 batch = 8192; barrier-free loop
    gru2_wp3_kernel<<<148, 224>>>(x, h, Wih0, Whh0, bih0, bhh0,
                                  Wih1, Whh1, bih1, bhh1, Wout, bout,
                                  (float*)d_out);
}